// round 1
// baseline (speedup 1.0000x reference)
#include <cuda_runtime.h>
#include <cstdint>

// Problem constants (from reference)
constexpr int Bn   = 256;
constexpr int Wn   = 512;
constexpr int Dn   = 256;
constexpr int Gn   = 8;
constexpr int DG   = 32;          // Dn / Gn
constexpr int Kc   = 9;           // CHEB_DEG + 1 coefficients
constexpr float DTc = 0.1f;

constexpr int TILE = 64;          // tokens per block along W
constexpr int HALO = 8;           // Chebyshev degree
constexpr int SPAN = TILE + 2 * HALO;  // 80

// Precomputed per-group propagator, stored TRANSPOSED: g_Pt[g][j][i] = P_g[i][j]
__device__ float g_Pt[Gn * DG * DG];

// ---------------------------------------------------------------------------
// Precompute P_g = M_g^4, M = I + dt*A + 0.5*dt^2*A^2,
// A = U V^T - V U^T - S S^T + (trR/dg) I   (all 32x32, per group)
// One block per group, 1024 threads = one (i,j) entry each.
// ---------------------------------------------------------------------------
__global__ void __launch_bounds__(1024) precompute_P(
    const float* __restrict__ U, const float* __restrict__ V,
    const float* __restrict__ S)
{
    const int g   = blockIdx.x;
    const int tid = threadIdx.x;
    const int i   = tid >> 5;     // out row
    const int j   = tid & 31;     // in col

    __shared__ float sU[DG * 16], sV[DG * 16], sS[DG * 16];
    __shared__ float A[DG * DG], M[DG * DG], T[DG * DG];
    __shared__ float trR;

    if (tid < DG * 16) {
        sU[tid] = U[g * DG * 16 + tid];
        sV[tid] = V[g * DG * 16 + tid];
        sS[tid] = S[g * DG * 16 + tid];
    }
    __syncthreads();

    if (tid < 32) {
        float s = 0.f;
        #pragma unroll
        for (int r = 0; r < 16; r++) { float v = sS[tid * 16 + r]; s += v * v; }
        #pragma unroll
        for (int o = 16; o; o >>= 1) s += __shfl_xor_sync(0xffffffffu, s, o);
        if (tid == 0) trR = s;
    }
    __syncthreads();

    float a = 0.f;
    #pragma unroll
    for (int r = 0; r < 16; r++) {
        a += sU[i * 16 + r] * sV[j * 16 + r]
           - sV[i * 16 + r] * sU[j * 16 + r]
           - sS[i * 16 + r] * sS[j * 16 + r];
    }
    if (i == j) a += trR * (1.f / DG);
    A[i * DG + j] = a;
    __syncthreads();

    float a2 = 0.f;
    #pragma unroll
    for (int k = 0; k < DG; k++) a2 += A[i * DG + k] * A[k * DG + j];
    float m = ((i == j) ? 1.f : 0.f) + DTc * a + 0.5f * DTc * DTc * a2;
    M[i * DG + j] = m;
    __syncthreads();

    // T = M^2
    float t = 0.f;
    #pragma unroll
    for (int k = 0; k < DG; k++) t += M[i * DG + k] * M[k * DG + j];
    T[i * DG + j] = t;
    __syncthreads();

    // P = T^2 = M^4 ; store transposed
    float p = 0.f;
    #pragma unroll
    for (int k = 0; k < DG; k++) p += T[i * DG + k] * T[k * DG + j];
    g_Pt[g * DG * DG + j * DG + i] = p;
}

// ---------------------------------------------------------------------------
// Fused: groupwise norm -> Chebyshev filter along W -> apply P_g
// One block per (W-tile, group, batch). 256 threads.
// ---------------------------------------------------------------------------
__global__ void __launch_bounds__(256) fused_kernel(
    const float* __restrict__ x, const float* __restrict__ cheb,
    float* __restrict__ out)
{
    const int wt = blockIdx.x;
    const int g  = blockIdx.y;
    const int b  = blockIdx.z;
    const int w0 = wt * TILE;

    __shared__ float tA[SPAN * DG];
    __shared__ float tB[SPAN * DG];
    __shared__ float yv[TILE * DG];
    __shared__ float Ps[DG * DG];
    __shared__ float c[Kc];

    const int tid  = threadIdx.x;
    const int lane = tid & 31;
    const int wp   = tid >> 5;

    const float* xb = x + ((size_t)b * Wn) * Dn + g * DG;

    // Load span (zeros outside [0, W))
    for (int e = tid; e < SPAN * DG; e += 256) {
        int tok = e >> 5, ch = e & 31;
        int w = w0 - HALO + tok;
        tA[e] = (w >= 0 && w < Wn) ? xb[(size_t)w * Dn + ch] : 0.f;
    }
    for (int e = tid; e < DG * DG; e += 256) Ps[e] = g_Pt[g * DG * DG + e];
    if (tid < Kc) c[tid] = cheb[g * Kc + tid];
    __syncthreads();

    // Groupwise norm: warp per token, lane = channel
    for (int tok = wp; tok < SPAN; tok += 8) {
        float v = tA[tok * DG + lane];
        float s = v;
        #pragma unroll
        for (int o = 16; o; o >>= 1) s += __shfl_xor_sync(0xffffffffu, s, o);
        float mean = s * (1.f / DG);
        float d = v - mean;
        float s2 = d * d;
        #pragma unroll
        for (int o = 16; o; o >>= 1) s2 += __shfl_xor_sync(0xffffffffu, s2, o);
        tA[tok * DG + lane] = d * rsqrtf(s2 * (1.f / DG) + 1e-6f);
    }
    __syncthreads();

    // t1 = Lhat(t0) with Dirichlet zeroing outside [0, W)
    for (int e = tid; e < SPAN * DG; e += 256) {
        int tok = e >> 5;
        int w = w0 - HALO + tok;
        float v = 0.f;
        if (w >= 0 && w < Wn) {
            float l = (tok > 0)        ? tA[e - DG] : 0.f;
            float r = (tok < SPAN - 1) ? tA[e + DG] : 0.f;
            v = -0.5f * (l + r);
        }
        tB[e] = v;
    }
    __syncthreads();

    // y = c0*t0 + c1*t1 on the central tile
    {
        float c0 = c[0], c1 = c[1];
        for (int e = tid; e < TILE * DG; e += 256)
            yv[e] = c0 * tA[e + HALO * DG] + c1 * tB[e + HALO * DG];
    }

    float* tp = tA;   // t_{k-2}
    float* tc = tB;   // t_{k-1}
    for (int k = 2; k < Kc; k++) {
        __syncthreads();
        // t_k = 2*Lhat(t_{k-1}) - t_{k-2} = -(tc[j-1]+tc[j+1]) - tp[j]
        for (int e = tid; e < SPAN * DG; e += 256) {
            int tok = e >> 5;
            int w = w0 - HALO + tok;
            float v = 0.f;
            if (w >= 0 && w < Wn) {
                float l = (tok > 0)        ? tc[e - DG] : 0.f;
                float r = (tok < SPAN - 1) ? tc[e + DG] : 0.f;
                v = -(l + r) - tp[e];
            }
            tp[e] = v;   // in-place into t_{k-2} slot
        }
        { float* tmp = tp; tp = tc; tc = tmp; }
        __syncthreads();
        float ck = c[k];
        for (int e = tid; e < TILE * DG; e += 256)
            yv[e] += ck * tc[e + HALO * DG];
    }
    __syncthreads();

    // z = P_g * y : warp per token, lane = out channel
    float* ob = out + ((size_t)b * Wn + w0) * Dn + g * DG;
    for (int tok = wp; tok < TILE; tok += 8) {
        const float* yrow = &yv[tok * DG];
        float acc = 0.f;
        #pragma unroll
        for (int j = 0; j < DG; j++)
            acc += Ps[j * DG + lane] * yrow[j];
        ob[(size_t)tok * Dn + lane] = acc;
    }
}

extern "C" void kernel_launch(void* const* d_in, const int* in_sizes, int n_in,
                              void* d_out, int out_size)
{
    const float* x    = (const float*)d_in[0];
    const float* cheb = (const float*)d_in[1];
    const float* U    = (const float*)d_in[2];
    const float* V    = (const float*)d_in[3];
    const float* S    = (const float*)d_in[4];
    float* out        = (float*)d_out;

    precompute_P<<<Gn, 1024>>>(U, V, S);
    dim3 grid(Wn / TILE, Gn, Bn);
    fused_kernel<<<grid, 256>>>(x, cheb, out);
}

// round 3
// speedup vs baseline: 1.6986x; 1.6986x over previous
#include <cuda_runtime.h>
#include <cstdint>

// Problem constants
constexpr int Bn   = 256;
constexpr int Wn   = 512;
constexpr int Dn   = 256;
constexpr int Gn   = 8;
constexpr int DG   = 32;
constexpr int Kc   = 9;          // CHEB_DEG + 1
constexpr float DTc = 0.1f;

constexpr int TPL  = 16;         // tokens per lane (32 lanes * 16 = 512 = Wn)
// Swizzled plane: addr(c,t) = c*ROWSZ + t + (t>>4)
//   ROWSZ = 545 == 1 (mod 32); intra-row pad every 16 tokens.
//   Phase A (fixed t, c varies): banks = c + const        -> conflict-free
//   Phase B (fixed c, t=16l+i):  banks = c + 17l + i      -> injective in l
//   Phase C (fixed t, j varies): same addr across lanes   -> broadcast
constexpr int ROWSZ = Wn + Wn / 16 + 1;   // 545
#define XADDR(c, t) ((c) * ROWSZ + (t) + ((t) >> 4))

// Precomputed per-group propagator, stored TRANSPOSED: g_Pt[g][j][i] = P_g[i][j]
__device__ float g_Pt[Gn * DG * DG];

// ---------------------------------------------------------------------------
// Precompute P_g = M_g^4, M = I + dt*A + 0.5*dt^2*A^2,
// A = U V^T - V U^T - S S^T + (trR/dg) I   (32x32 per group)
// ---------------------------------------------------------------------------
__global__ void __launch_bounds__(1024) precompute_P(
    const float* __restrict__ U, const float* __restrict__ V,
    const float* __restrict__ S)
{
    const int g   = blockIdx.x;
    const int tid = threadIdx.x;
    const int i   = tid >> 5;
    const int j   = tid & 31;

    __shared__ float sU[DG * 16], sV[DG * 16], sS[DG * 16];
    __shared__ float A[DG * DG], M[DG * DG], T[DG * DG];
    __shared__ float trR;

    if (tid < DG * 16) {
        sU[tid] = U[g * DG * 16 + tid];
        sV[tid] = V[g * DG * 16 + tid];
        sS[tid] = S[g * DG * 16 + tid];
    }
    __syncthreads();

    if (tid < 32) {
        float s = 0.f;
        #pragma unroll
        for (int r = 0; r < 16; r++) { float v = sS[tid * 16 + r]; s += v * v; }
        #pragma unroll
        for (int o = 16; o; o >>= 1) s += __shfl_xor_sync(0xffffffffu, s, o);
        if (tid == 0) trR = s;
    }
    __syncthreads();

    float a = 0.f;
    #pragma unroll
    for (int r = 0; r < 16; r++) {
        a += sU[i * 16 + r] * sV[j * 16 + r]
           - sV[i * 16 + r] * sU[j * 16 + r]
           - sS[i * 16 + r] * sS[j * 16 + r];
    }
    if (i == j) a += trR * (1.f / DG);
    A[i * DG + j] = a;
    __syncthreads();

    float a2 = 0.f;
    #pragma unroll
    for (int k = 0; k < DG; k++) a2 += A[i * DG + k] * A[k * DG + j];
    float m = ((i == j) ? 1.f : 0.f) + DTc * a + 0.5f * DTc * DTc * a2;
    M[i * DG + j] = m;
    __syncthreads();

    float t = 0.f;
    #pragma unroll
    for (int k = 0; k < DG; k++) t += M[i * DG + k] * M[k * DG + j];
    T[i * DG + j] = t;
    __syncthreads();

    float p = 0.f;
    #pragma unroll
    for (int k = 0; k < DG; k++) p += T[i * DG + k] * T[k * DG + j];
    g_Pt[g * DG * DG + j * DG + i] = p;
}

// ---------------------------------------------------------------------------
// Fused: norm -> register-resident Chebyshev along full W -> P_g matvec.
// One CTA per (g, b). 256 threads = 8 warps. Each warp owns 4 channel rows
// for the recursion; lane l holds tokens [16l, 16l+16) in registers.
// ---------------------------------------------------------------------------
__global__ void __launch_bounds__(256) fused2(
    const float* __restrict__ x, const float* __restrict__ cheb,
    float* __restrict__ out)
{
    const int g  = blockIdx.x;
    const int b  = blockIdx.y;

    extern __shared__ float xs[];           // swizzled [DG][ROWSZ] plane
    __shared__ float Ps[DG * DG];           // P^T for this group
    __shared__ float cc[Kc];

    const int tid  = threadIdx.x;
    const int lane = tid & 31;
    const int wp   = tid >> 5;

    for (int e = tid; e < DG * DG; e += 256) Ps[e] = g_Pt[g * DG * DG + e];
    if (tid < Kc) cc[tid] = cheb[g * Kc + tid];

    // ---- Phase A: load + groupwise norm (warp per token, lane = channel) ----
    const float* xb = x + ((size_t)b * Wn) * Dn + g * DG;
    for (int t = wp; t < Wn; t += 8) {
        float v = xb[(size_t)t * Dn + lane];
        float s = v;
        #pragma unroll
        for (int o = 16; o; o >>= 1) s += __shfl_xor_sync(0xffffffffu, s, o);
        float mean = s * (1.f / DG);
        float d = v - mean;
        float s2 = d * d;
        #pragma unroll
        for (int o = 16; o; o >>= 1) s2 += __shfl_xor_sync(0xffffffffu, s2, o);
        xs[XADDR(lane, t)] = d * rsqrtf(s2 * (1.f / DG) + 1e-6f);
    }
    __syncthreads();

    // ---- Phase B: Chebyshev recursion in registers, warp per channel row ----
    const float c0 = cc[0], c1 = cc[1];
    const float c2 = cc[2], c3 = cc[3], c4 = cc[4];
    const float c5 = cc[5], c6 = cc[6], c7 = cc[7], c8 = cc[8];

    #pragma unroll
    for (int q = 0; q < 4; q++) {
        const int c = wp * 4 + q;
        const int base = c * ROWSZ + 17 * lane;   // XADDR(c, 16*lane) ; +i for token 16*lane+i
        float A_[TPL], B_[TPL], y_[TPL];

        #pragma unroll
        for (int i = 0; i < TPL; i++) A_[i] = xs[base + i];

        // t1 = Lhat(t0), Dirichlet boundaries at w=-1 and w=Wn
        {
            float lh = __shfl_up_sync(0xffffffffu, A_[TPL - 1], 1);
            float rh = __shfl_down_sync(0xffffffffu, A_[0], 1);
            if (lane == 0)  lh = 0.f;
            if (lane == 31) rh = 0.f;
            #pragma unroll
            for (int i = 0; i < TPL; i++) {
                float L = (i > 0)       ? A_[i - 1] : lh;
                float R = (i < TPL - 1) ? A_[i + 1] : rh;
                B_[i] = -0.5f * (L + R);
                y_[i] = c0 * A_[i] + c1 * B_[i];
            }
        }

        // t_k = -(t_{k-1}[j-1] + t_{k-1}[j+1]) - t_{k-2}, overwrites PREV
        #define CHEB_STEP(PREV, CUR, CK)                                       \
        {                                                                      \
            float lh = __shfl_up_sync(0xffffffffu, CUR[TPL - 1], 1);           \
            float rh = __shfl_down_sync(0xffffffffu, CUR[0], 1);               \
            if (lane == 0)  lh = 0.f;                                          \
            if (lane == 31) rh = 0.f;                                          \
            _Pragma("unroll")                                                  \
            for (int i = 0; i < TPL; i++) {                                    \
                float L = (i > 0)       ? CUR[i - 1] : lh;                     \
                float R = (i < TPL - 1) ? CUR[i + 1] : rh;                     \
                float nt = -(L + R) - PREV[i];                                 \
                y_[i] += (CK) * nt;                                            \
                PREV[i] = nt;                                                  \
            }                                                                  \
        }
        CHEB_STEP(A_, B_, c2)
        CHEB_STEP(B_, A_, c3)
        CHEB_STEP(A_, B_, c4)
        CHEB_STEP(B_, A_, c5)
        CHEB_STEP(A_, B_, c6)
        CHEB_STEP(B_, A_, c7)
        CHEB_STEP(A_, B_, c8)
        #undef CHEB_STEP

        #pragma unroll
        for (int i = 0; i < TPL; i++) xs[base + i] = y_[i];
    }
    __syncthreads();

    // ---- Phase C: z = P_g * y. Warp per token, lane = out channel. ----
    float pcol[DG];
    #pragma unroll
    for (int j = 0; j < DG; j++) pcol[j] = Ps[j * DG + lane];   // P[lane][j]

    float* ob = out + ((size_t)b * Wn) * Dn + g * DG;
    for (int t = wp; t < Wn; t += 8) {
        const int ta = t + (t >> 4);
        float acc = 0.f;
        #pragma unroll
        for (int j = 0; j < DG; j++)
            acc += pcol[j] * xs[j * ROWSZ + ta];   // broadcast across lanes
        ob[(size_t)t * Dn + lane] = acc;
    }
}

extern "C" void kernel_launch(void* const* d_in, const int* in_sizes, int n_in,
                              void* d_out, int out_size)
{
    const float* x    = (const float*)d_in[0];
    const float* cheb = (const float*)d_in[1];
    const float* U    = (const float*)d_in[2];
    const float* V    = (const float*)d_in[3];
    const float* S    = (const float*)d_in[4];
    float* out        = (float*)d_out;

    const int dyn_smem = DG * ROWSZ * (int)sizeof(float);   // 69760 B
    cudaFuncSetAttribute(fused2, cudaFuncAttributeMaxDynamicSharedMemorySize, dyn_smem);

    precompute_P<<<Gn, 1024>>>(U, V, S);
    dim3 grid(Gn, Bn);
    fused2<<<grid, 256, dyn_smem>>>(x, cheb, out);
}

// round 4
// speedup vs baseline: 2.2897x; 1.3480x over previous
#include <cuda_runtime.h>
#include <cstdint>

// Problem constants
constexpr int Bn = 256, Wn = 512, Dn = 256, Gn = 8, DG = 32, Kc = 9;
constexpr float DTc = 0.1f;

// Chunking along W
constexpr int HALO   = 8;
constexpr int CUSE   = 112;            // useful tokens per chunk
constexpr int SPAN   = 128;            // CUSE + 2*HALO
constexpr int NCHUNK = 5;              // ceil(Wn / CUSE)
constexpr int TPL    = 4;              // span tokens per lane (32*4 = 128)

// x-plane (channel-major): addr(c,t) = c*XROW + t + (t>>2)
//   Phase A store (fixed t, lanes=c): bank = c + const      -> conflict-free
//   Phase B load  (fixed c, t=4l+i):  bank = c + 5l + i     -> injective in l
constexpr int XROW = 161;              // odd
// y-plane (token-major, aliased onto x-plane): addr(t,c) = t*YROW + (c ^ 4*((t>>2)&7))
//   16B-aligned rows -> Phase C reads 8x LDS.128 broadcast per token
constexpr int YROW = 36;               // multiple of 4
constexpr int XS_FLOATS = DG * XROW;   // 5152 >= max y addr 4607

// Precomputed per-group propagator, TRANSPOSED: g_Pt[g][j][i] = P_g[i][j]
__device__ float g_Pt[Gn * DG * DG];

// ---------------------------------------------------------------------------
// Precompute P_g = M_g^4, M = I + dt*A + 0.5*dt^2*A^2,
// A = U V^T - V U^T - S S^T + (trR/dg) I   (32x32 per group)
// ---------------------------------------------------------------------------
__global__ void __launch_bounds__(1024) precompute_P(
    const float* __restrict__ U, const float* __restrict__ V,
    const float* __restrict__ S)
{
    const int g   = blockIdx.x;
    const int tid = threadIdx.x;
    const int i   = tid >> 5;
    const int j   = tid & 31;

    __shared__ float sU[DG * 16], sV[DG * 16], sS[DG * 16];
    __shared__ float A[DG * DG], M[DG * DG], T[DG * DG];
    __shared__ float trR;

    if (tid < DG * 16) {
        sU[tid] = U[g * DG * 16 + tid];
        sV[tid] = V[g * DG * 16 + tid];
        sS[tid] = S[g * DG * 16 + tid];
    }
    __syncthreads();

    if (tid < 32) {
        float s = 0.f;
        #pragma unroll
        for (int r = 0; r < 16; r++) { float v = sS[tid * 16 + r]; s += v * v; }
        #pragma unroll
        for (int o = 16; o; o >>= 1) s += __shfl_xor_sync(0xffffffffu, s, o);
        if (tid == 0) trR = s;
    }
    __syncthreads();

    float a = 0.f;
    #pragma unroll
    for (int r = 0; r < 16; r++) {
        a += sU[i * 16 + r] * sV[j * 16 + r]
           - sV[i * 16 + r] * sU[j * 16 + r]
           - sS[i * 16 + r] * sS[j * 16 + r];
    }
    if (i == j) a += trR * (1.f / DG);
    A[i * DG + j] = a;
    __syncthreads();

    float a2 = 0.f;
    #pragma unroll
    for (int k = 0; k < DG; k++) a2 += A[i * DG + k] * A[k * DG + j];
    float m = ((i == j) ? 1.f : 0.f) + DTc * a + 0.5f * DTc * DTc * a2;
    M[i * DG + j] = m;
    __syncthreads();

    float t = 0.f;
    #pragma unroll
    for (int k = 0; k < DG; k++) t += M[i * DG + k] * M[k * DG + j];
    T[i * DG + j] = t;
    __syncthreads();

    float p = 0.f;
    #pragma unroll
    for (int k = 0; k < DG; k++) p += T[i * DG + k] * T[k * DG + j];
    g_Pt[g * DG * DG + j * DG + i] = p;
}

// ---------------------------------------------------------------------------
// Fused: norm -> register Chebyshev (chunked, halo-8) -> vectorized P matvec
// CTA = (chunk, g, b). 256 threads = 8 warps.
// ---------------------------------------------------------------------------
__global__ void __launch_bounds__(256) fused3(
    const float* __restrict__ x, const float* __restrict__ cheb,
    float* __restrict__ out)
{
    const int chn = blockIdx.x;
    const int g   = blockIdx.y;
    const int b   = blockIdx.z;
    const int w0  = chn * CUSE - HALO;      // global w of span-local token 0

    __shared__ __align__(16) float xs[XS_FLOATS];
    __shared__ float Ps[DG * DG];
    __shared__ float cc[Kc];

    const int tid  = threadIdx.x;
    const int lane = tid & 31;
    const int wp   = tid >> 5;

    for (int e = tid; e < DG * DG; e += 256) Ps[e] = g_Pt[g * DG * DG + e];
    if (tid < Kc) cc[tid] = cheb[g * Kc + tid];

    // ---- Phase A: float4 load + octet norm + store to x-plane ----
    // 8 lanes per token (4 channels each), 4 tokens per pass, 4 passes/warp.
    const int cq   = (lane & 7) * 4;        // channel base for this lane
    const int tsub = lane >> 3;             // token within pass
    const float* xg = x + ((size_t)b * Wn) * Dn + g * DG + cq;
    #pragma unroll
    for (int p = 0; p < 4; p++) {
        int t = wp * 16 + p * 4 + tsub;     // span-local token 0..127
        int w = w0 + t;
        float4 v = make_float4(0.f, 0.f, 0.f, 0.f);
        if (w >= 0 && w < Wn) v = *(const float4*)(xg + (size_t)w * Dn);
        float s1 = v.x + v.y + v.z + v.w;
        float s2 = v.x * v.x + v.y * v.y + v.z * v.z + v.w * v.w;
        #pragma unroll
        for (int o = 1; o < 8; o <<= 1) {
            s1 += __shfl_xor_sync(0xffffffffu, s1, o);
            s2 += __shfl_xor_sync(0xffffffffu, s2, o);
        }
        float mean = s1 * (1.f / DG);
        float var  = s2 * (1.f / DG) - mean * mean;
        float rstd = rsqrtf(var + 1e-6f);
        int fb = t + (t >> 2);
        xs[(cq + 0) * XROW + fb] = (v.x - mean) * rstd;
        xs[(cq + 1) * XROW + fb] = (v.y - mean) * rstd;
        xs[(cq + 2) * XROW + fb] = (v.z - mean) * rstd;
        xs[(cq + 3) * XROW + fb] = (v.w - mean) * rstd;
    }
    __syncthreads();

    // ---- Preload all 4 channel rows (all x-plane reads before y overwrite) ----
    float A4[4][TPL];
    #pragma unroll
    for (int q = 0; q < 4; q++) {
        const int base = (wp * 4 + q) * XROW + 5 * lane;   // token 4l+i -> +i
        #pragma unroll
        for (int i = 0; i < TPL; i++) A4[q][i] = xs[base + i];
    }
    // Dirichlet mask for true domain boundaries
    float mk[TPL];
    #pragma unroll
    for (int i = 0; i < TPL; i++) {
        int w = w0 + 4 * lane + i;
        mk[i] = (w >= 0 && w < Wn) ? 1.f : 0.f;
    }
    __syncthreads();

    const float c0 = cc[0], c1 = cc[1], c2 = cc[2], c3 = cc[3], c4 = cc[4];
    const float c5 = cc[5], c6 = cc[6], c7 = cc[7], c8 = cc[8];

    // ---- Phase B: register Chebyshev recursion; store y token-major ----
    const int swb = 4 * (lane & 7);          // swizzle bits for tokens 4l..4l+3
    #pragma unroll
    for (int q = 0; q < 4; q++) {
        const int c = wp * 4 + q;
        float X[TPL], T[TPL], y[TPL];
        #pragma unroll
        for (int i = 0; i < TPL; i++) X[i] = A4[q][i];

        {   // t1 = Lhat(t0) (masked)
            float lh = __shfl_up_sync(0xffffffffu, X[TPL - 1], 1);
            float rh = __shfl_down_sync(0xffffffffu, X[0], 1);
            if (lane == 0)  lh = 0.f;
            if (lane == 31) rh = 0.f;
            #pragma unroll
            for (int i = 0; i < TPL; i++) {
                float L = (i > 0)       ? X[i - 1] : lh;
                float R = (i < TPL - 1) ? X[i + 1] : rh;
                T[i] = -0.5f * (L + R) * mk[i];
                y[i] = c0 * X[i] + c1 * T[i];
            }
        }
        #define STEP(PV, CU, CK)                                              \
        {                                                                     \
            float lh = __shfl_up_sync(0xffffffffu, CU[TPL - 1], 1);           \
            float rh = __shfl_down_sync(0xffffffffu, CU[0], 1);               \
            if (lane == 0)  lh = 0.f;                                         \
            if (lane == 31) rh = 0.f;                                         \
            _Pragma("unroll")                                                 \
            for (int i = 0; i < TPL; i++) {                                   \
                float L = (i > 0)       ? CU[i - 1] : lh;                     \
                float R = (i < TPL - 1) ? CU[i + 1] : rh;                     \
                float nt = (-(L + R) - PV[i]) * mk[i];                        \
                y[i] += (CK) * nt;                                            \
                PV[i] = nt;                                                   \
            }                                                                 \
        }
        STEP(X, T, c2) STEP(T, X, c3) STEP(X, T, c4) STEP(T, X, c5)
        STEP(X, T, c6) STEP(T, X, c7) STEP(X, T, c8)
        #undef STEP

        #pragma unroll
        for (int i = 0; i < TPL; i++)
            xs[(4 * lane + i) * YROW + (c ^ swb)] = y[i];
    }
    __syncthreads();

    // ---- Phase C: z = P * y via float4 broadcast reads. Warp per token. ----
    float pcol[DG];
    #pragma unroll
    for (int j = 0; j < DG; j++) pcol[j] = Ps[j * DG + lane];   // P[lane][j]

    const float4* xs4 = (const float4*)xs;
    float* ob = out + ((size_t)b * Wn) * Dn + g * DG + lane;
    for (int t = HALO + wp; t < HALO + CUSE; t += 8) {
        int w = w0 + t;
        if (w >= Wn) break;                 // only trims the last chunk
        int b9 = t * 9;                     // (t*YROW)/4
        int sw = (t >> 2) & 7;
        float acc = 0.f;
        #pragma unroll
        for (int k = 0; k < 8; k++) {
            float4 yv = xs4[b9 + (k ^ sw)];
            acc += pcol[4 * k + 0] * yv.x + pcol[4 * k + 1] * yv.y
                 + pcol[4 * k + 2] * yv.z + pcol[4 * k + 3] * yv.w;
        }
        ob[(size_t)w * Dn] = acc;
    }
}

extern "C" void kernel_launch(void* const* d_in, const int* in_sizes, int n_in,
                              void* d_out, int out_size)
{
    const float* x    = (const float*)d_in[0];
    const float* cheb = (const float*)d_in[1];
    const float* U    = (const float*)d_in[2];
    const float* V    = (const float*)d_in[3];
    const float* S    = (const float*)d_in[4];
    float* out        = (float*)d_out;

    precompute_P<<<Gn, 1024>>>(U, V, S);
    dim3 grid(NCHUNK, Gn, Bn);
    fused3<<<grid, 256>>>(x, cheb, out);
}

// round 5
// speedup vs baseline: 2.5722x; 1.1234x over previous
#include <cuda_runtime.h>
#include <cstdint>

// Problem constants
constexpr int Bn = 256, Wn = 512, Dn = 256, Gn = 8, DG = 32, Kc = 9;
constexpr float DTc = 0.1f;

// Chunking along W
constexpr int HALO   = 8;
constexpr int CUSE   = 112;
constexpr int SPAN   = 128;
constexpr int NCHUNK = 5;
constexpr int TPL    = 4;     // span tokens per lane

// x-plane (channel-major): addr(c,t) = c*XROW + t + (t>>2); conflict-free
constexpr int XROW = 161;
// y-plane (token-major): float addr = t*YROW + (c ^ 4*((t>>2)&7)); 16B rows
constexpr int YROW = 36;

typedef unsigned long long u64x2;

#define PK2(d, a, b)    asm("mov.b64 %0,{%1,%2};" : "=l"(d) : "f"(a), "f"(b))
#define UPK2(a, b, d)   asm("mov.b64 {%0,%1},%2;" : "=f"(a), "=f"(b) : "l"(d))
#define FMA2(d, a, b, c) asm("fma.rn.f32x2 %0,%1,%2,%3;" : "=l"(d) : "l"(a), "l"(b), "l"(c))
#define ADD2(d, a, b)   asm("add.rn.f32x2 %0,%1,%2;" : "=l"(d) : "l"(a), "l"(b))
#define MUL2(d, a, b)   asm("mul.rn.f32x2 %0,%1,%2;" : "=l"(d) : "l"(a), "l"(b))

// Precomputed per-group propagator, TRANSPOSED: g_Pt[g][j][i] = P_g[i][j]
__device__ float g_Pt[Gn * DG * DG];

// ---------------------------------------------------------------------------
// Precompute P_g = M_g^4, M = I + dt*A + 0.5*dt^2*A^2,
// A = U V^T - V U^T - S S^T + (trR/dg) I   (32x32 per group)
// ---------------------------------------------------------------------------
__global__ void __launch_bounds__(1024) precompute_P(
    const float* __restrict__ U, const float* __restrict__ V,
    const float* __restrict__ S)
{
    const int g   = blockIdx.x;
    const int tid = threadIdx.x;
    const int i   = tid >> 5;
    const int j   = tid & 31;

    __shared__ float sU[DG * 16], sV[DG * 16], sS[DG * 16];
    __shared__ float A[DG * DG], M[DG * DG], T[DG * DG];
    __shared__ float trR;

    if (tid < DG * 16) {
        sU[tid] = U[g * DG * 16 + tid];
        sV[tid] = V[g * DG * 16 + tid];
        sS[tid] = S[g * DG * 16 + tid];
    }
    __syncthreads();

    if (tid < 32) {
        float s = 0.f;
        #pragma unroll
        for (int r = 0; r < 16; r++) { float v = sS[tid * 16 + r]; s += v * v; }
        #pragma unroll
        for (int o = 16; o; o >>= 1) s += __shfl_xor_sync(0xffffffffu, s, o);
        if (tid == 0) trR = s;
    }
    __syncthreads();

    float a = 0.f;
    #pragma unroll
    for (int r = 0; r < 16; r++) {
        a += sU[i * 16 + r] * sV[j * 16 + r]
           - sV[i * 16 + r] * sU[j * 16 + r]
           - sS[i * 16 + r] * sS[j * 16 + r];
    }
    if (i == j) a += trR * (1.f / DG);
    A[i * DG + j] = a;
    __syncthreads();

    float a2 = 0.f;
    #pragma unroll
    for (int k = 0; k < DG; k++) a2 += A[i * DG + k] * A[k * DG + j];
    float m = ((i == j) ? 1.f : 0.f) + DTc * a + 0.5f * DTc * DTc * a2;
    M[i * DG + j] = m;
    __syncthreads();

    float t = 0.f;
    #pragma unroll
    for (int k = 0; k < DG; k++) t += M[i * DG + k] * M[k * DG + j];
    T[i * DG + j] = t;
    __syncthreads();

    float p = 0.f;
    #pragma unroll
    for (int k = 0; k < DG; k++) p += T[i * DG + k] * T[k * DG + j];
    g_Pt[g * DG * DG + j * DG + i] = p;
}

// ---------------------------------------------------------------------------
// Fused: norm -> f32x2 channel-packed Chebyshev -> f32x2 K-packed P matvec
// CTA = (chunk, g, b). 256 threads = 8 warps.
// ---------------------------------------------------------------------------
__global__ void __launch_bounds__(256) fused4(
    const float* __restrict__ x, const float* __restrict__ cheb,
    float* __restrict__ out)
{
    const int chn = blockIdx.x;
    const int g   = blockIdx.y;
    const int b   = blockIdx.z;
    const int w0  = chn * CUSE - HALO;

    __shared__ float xs[DG * XROW];                    // x-plane (channel-major)
    __shared__ __align__(16) float ys[SPAN * YROW];    // y-plane (token-major)
    __shared__ float Ps[DG * DG];
    __shared__ float cc[Kc];

    const int tid  = threadIdx.x;
    const int lane = tid & 31;
    const int wp   = tid >> 5;

    for (int e = tid; e < DG * DG; e += 256) Ps[e] = g_Pt[g * DG * DG + e];
    // sign-flipped coefficients for u-recursion: u_k = (-1)^k t_k
    if (tid < Kc) cc[tid] = cheb[g * Kc + tid] * ((tid & 1) ? -1.f : 1.f);

    // ---- Phase A: float4 load + octet norm -> x-plane ----
    const int cq   = (lane & 7) * 4;
    const int tsub = lane >> 3;
    const float* xg = x + ((size_t)b * Wn) * Dn + g * DG + cq;
    #pragma unroll
    for (int p = 0; p < 4; p++) {
        int t = wp * 16 + p * 4 + tsub;
        int w = w0 + t;
        float4 v = make_float4(0.f, 0.f, 0.f, 0.f);
        if (w >= 0 && w < Wn) v = *(const float4*)(xg + (size_t)w * Dn);
        float s1 = v.x + v.y + v.z + v.w;
        float s2 = v.x * v.x + v.y * v.y + v.z * v.z + v.w * v.w;
        #pragma unroll
        for (int o = 1; o < 8; o <<= 1) {
            s1 += __shfl_xor_sync(0xffffffffu, s1, o);
            s2 += __shfl_xor_sync(0xffffffffu, s2, o);
        }
        float mean = s1 * (1.f / DG);
        float var  = s2 * (1.f / DG) - mean * mean;
        float rstd = rsqrtf(var + 1e-6f);
        int fb = t + (t >> 2);
        xs[(cq + 0) * XROW + fb] = (v.x - mean) * rstd;
        xs[(cq + 1) * XROW + fb] = (v.y - mean) * rstd;
        xs[(cq + 2) * XROW + fb] = (v.z - mean) * rstd;
        xs[(cq + 3) * XROW + fb] = (v.w - mean) * rstd;
    }
    __syncthreads();

    // ---- Phase B: channel-pair packed u-recursion (u_k = S u_{k-1} - u_{k-2})
    u64x2 NEG2, H2;
    PK2(NEG2, -1.f, -1.f);
    PK2(H2, 0.5f, 0.5f);
    u64x2 mk2[TPL];
    #pragma unroll
    for (int i = 0; i < TPL; i++) {
        int w = w0 + 4 * lane + i;
        float m = (w >= 0 && w < Wn) ? 1.f : 0.f;
        PK2(mk2[i], m, m);
    }
    const int swb = 4 * (lane & 7);

    #pragma unroll
    for (int p = 0; p < 2; p++) {
        const int cA = wp * 4 + 2 * p;           // even channel of the pair
        u64x2 X2[TPL], T2[TPL], y2[TPL];

        #pragma unroll
        for (int i = 0; i < TPL; i++)
            PK2(X2[i], xs[cA * XROW + 5 * lane + i],
                        xs[(cA + 1) * XROW + 5 * lane + i]);

        // u1 = 0.5 * S(u0) * mk ; y = c0*u0 + cc1*u1
        {
            float el, eh, fl, fh;
            UPK2(el, eh, X2[TPL - 1]);
            UPK2(fl, fh, X2[0]);
            float l0 = __shfl_up_sync(0xffffffffu, el, 1);
            float l1 = __shfl_up_sync(0xffffffffu, eh, 1);
            float r0 = __shfl_down_sync(0xffffffffu, fl, 1);
            float r1 = __shfl_down_sync(0xffffffffu, fh, 1);
            u64x2 lh2 = 0ull, rh2 = 0ull;
            if (lane != 0)  PK2(lh2, l0, l1);
            if (lane != 31) PK2(rh2, r0, r1);
            u64x2 c02, c12;
            PK2(c02, cc[0], cc[0]);
            PK2(c12, cc[1], cc[1]);
            #pragma unroll
            for (int i = 0; i < TPL; i++) {
                u64x2 L = (i > 0)       ? X2[i - 1] : lh2;
                u64x2 R = (i < TPL - 1) ? X2[i + 1] : rh2;
                u64x2 s; ADD2(s, L, R);
                MUL2(s, s, H2);
                MUL2(s, s, mk2[i]);
                T2[i] = s;
                u64x2 tmp; MUL2(tmp, c02, X2[i]);
                FMA2(y2[i], c12, T2[i], tmp);
            }
        }

        // u_k = S(u_{k-1}) - u_{k-2} (masked); y += cc_k * u_k
        #define STEPP(PV, CU, CKV)                                            \
        {                                                                     \
            float el, eh, fl, fh;                                             \
            UPK2(el, eh, CU[TPL - 1]);                                        \
            UPK2(fl, fh, CU[0]);                                              \
            float l0 = __shfl_up_sync(0xffffffffu, el, 1);                    \
            float l1 = __shfl_up_sync(0xffffffffu, eh, 1);                    \
            float r0 = __shfl_down_sync(0xffffffffu, fl, 1);                  \
            float r1 = __shfl_down_sync(0xffffffffu, fh, 1);                  \
            u64x2 lh2 = 0ull, rh2 = 0ull;                                     \
            if (lane != 0)  PK2(lh2, l0, l1);                                 \
            if (lane != 31) PK2(rh2, r0, r1);                                 \
            u64x2 ck2; PK2(ck2, CKV, CKV);                                    \
            _Pragma("unroll")                                                 \
            for (int i = 0; i < TPL; i++) {                                   \
                u64x2 L = (i > 0)       ? CU[i - 1] : lh2;                    \
                u64x2 R = (i < TPL - 1) ? CU[i + 1] : rh2;                    \
                u64x2 s; ADD2(s, L, R);                                       \
                u64x2 nt; FMA2(nt, PV[i], NEG2, s);                           \
                MUL2(nt, nt, mk2[i]);                                         \
                FMA2(y2[i], ck2, nt, y2[i]);                                  \
                PV[i] = nt;                                                   \
            }                                                                 \
        }
        STEPP(X2, T2, cc[2])
        STEPP(T2, X2, cc[3])
        STEPP(X2, T2, cc[4])
        STEPP(T2, X2, cc[5])
        STEPP(X2, T2, cc[6])
        STEPP(T2, X2, cc[7])
        STEPP(X2, T2, cc[8])
        #undef STEPP

        // store y pair: STS.64 at swizzled slot (swb even -> pair stays adjacent)
        #pragma unroll
        for (int i = 0; i < TPL; i++) {
            float lo, hi;
            UPK2(lo, hi, y2[i]);
            int fo = (4 * lane + i) * YROW + (cA ^ swb);
            *(float2*)&ys[fo] = make_float2(lo, hi);
        }
    }
    __syncthreads();

    // ---- Phase C: z = P*y, K-dim packed f32x2. Warp per token, lane = channel
    u64x2 pa[8], pb[8];
    #pragma unroll
    for (int k = 0; k < 8; k++) {
        PK2(pa[k], Ps[(4 * k + 0) * DG + lane], Ps[(4 * k + 1) * DG + lane]);
        PK2(pb[k], Ps[(4 * k + 2) * DG + lane], Ps[(4 * k + 3) * DG + lane]);
    }
    const uint32_t ysb = (uint32_t)__cvta_generic_to_shared(ys);
    float* ob = out + ((size_t)b * Wn) * Dn + g * DG + lane;

    for (int t = HALO + wp; t < HALO + CUSE; t += 8) {
        int w = w0 + t;
        if (w >= Wn) break;
        const int sw = (t >> 2) & 7;
        const uint32_t ba = ysb + (uint32_t)t * (YROW * 4);
        u64x2 a0 = 0ull, a1 = 0ull;
        #pragma unroll
        for (int k = 0; k < 8; k++) {
            uint32_t ad = ba + 16u * (uint32_t)(k ^ sw);
            u64x2 ya, yb;
            asm volatile("ld.shared.v2.u64 {%0,%1},[%2];"
                         : "=l"(ya), "=l"(yb) : "r"(ad));
            FMA2(a0, ya, pa[k], a0);
            FMA2(a1, yb, pb[k], a1);
        }
        float x0, x1, x2, x3;
        UPK2(x0, x1, a0);
        UPK2(x2, x3, a1);
        ob[(size_t)w * Dn] = (x0 + x1) + (x2 + x3);
    }
}

extern "C" void kernel_launch(void* const* d_in, const int* in_sizes, int n_in,
                              void* d_out, int out_size)
{
    const float* x    = (const float*)d_in[0];
    const float* cheb = (const float*)d_in[1];
    const float* U    = (const float*)d_in[2];
    const float* V    = (const float*)d_in[3];
    const float* S    = (const float*)d_in[4];
    float* out        = (float*)d_out;

    precompute_P<<<Gn, 1024>>>(U, V, S);
    dim3 grid(NCHUNK, Gn, Bn);
    fused4<<<grid, 256>>>(x, cheb, out);
}

// round 6
// speedup vs baseline: 2.6542x; 1.0319x over previous
#include <cuda_runtime.h>
#include <cstdint>

// Problem constants
constexpr int Bn = 256, Wn = 512, Dn = 256, Gn = 8, DG = 32, Kc = 9;
constexpr float DTc = 0.1f;

// Chunking along W
constexpr int HALO = 8;
constexpr int CUSE = 112;
constexpr int SPAN = 128;
constexpr int TPL  = 4;      // span tokens per lane

// Pair-interleaved x-plane in float2 units: addr2(cp,t) = cp*PR2 + t + (t>>2)
//   Phase A store (fixed t, cp varies): ~2-way, same wavefronts as 4x STS.32
//   Phase B load  (fixed cp, t=4l+i):  addr2 = cp*PR2 + 5l + i, ~2-way
constexpr int PR2 = 161;     // odd
// y-plane (token-major floats): addr = t*YROW + (c ^ 4*((t>>2)&7)); 16B rows
constexpr int YROW = 36;

typedef unsigned long long u64x2;

#define PK2(d, a, b)     asm("mov.b64 %0,{%1,%2};" : "=l"(d) : "f"(a), "f"(b))
#define UPK2(a, b, d)    asm("mov.b64 {%0,%1},%2;" : "=f"(a), "=f"(b) : "l"(d))
#define FMA2(d, a, b, c) asm("fma.rn.f32x2 %0,%1,%2,%3;" : "=l"(d) : "l"(a), "l"(b), "l"(c))
#define ADD2(d, a, b)    asm("add.rn.f32x2 %0,%1,%2;" : "=l"(d) : "l"(a), "l"(b))
#define MUL2(d, a, b)    asm("mul.rn.f32x2 %0,%1,%2;" : "=l"(d) : "l"(a), "l"(b))

// Precomputed per-group propagator, TRANSPOSED: g_Pt[g][j][i] = P_g[i][j]
__device__ float g_Pt[Gn * DG * DG];

// ---------------------------------------------------------------------------
// Precompute P_g = M_g^4, M = I + dt*A + 0.5*dt^2*A^2,
// A = U V^T - V U^T - S S^T + (trR/dg) I   (32x32 per group)
// ---------------------------------------------------------------------------
__global__ void __launch_bounds__(1024) precompute_P(
    const float* __restrict__ U, const float* __restrict__ V,
    const float* __restrict__ S)
{
    const int g   = blockIdx.x;
    const int tid = threadIdx.x;
    const int i   = tid >> 5;
    const int j   = tid & 31;

    __shared__ float sU[DG * 16], sV[DG * 16], sS[DG * 16];
    __shared__ float A[DG * DG], M[DG * DG], T[DG * DG];
    __shared__ float trR;

    if (tid < DG * 16) {
        sU[tid] = U[g * DG * 16 + tid];
        sV[tid] = V[g * DG * 16 + tid];
        sS[tid] = S[g * DG * 16 + tid];
    }
    __syncthreads();

    if (tid < 32) {
        float s = 0.f;
        #pragma unroll
        for (int r = 0; r < 16; r++) { float v = sS[tid * 16 + r]; s += v * v; }
        #pragma unroll
        for (int o = 16; o; o >>= 1) s += __shfl_xor_sync(0xffffffffu, s, o);
        if (tid == 0) trR = s;
    }
    __syncthreads();

    float a = 0.f;
    #pragma unroll
    for (int r = 0; r < 16; r++) {
        a += sU[i * 16 + r] * sV[j * 16 + r]
           - sV[i * 16 + r] * sU[j * 16 + r]
           - sS[i * 16 + r] * sS[j * 16 + r];
    }
    if (i == j) a += trR * (1.f / DG);
    A[i * DG + j] = a;
    __syncthreads();

    float a2 = 0.f;
    #pragma unroll
    for (int k = 0; k < DG; k++) a2 += A[i * DG + k] * A[k * DG + j];
    float m = ((i == j) ? 1.f : 0.f) + DTc * a + 0.5f * DTc * DTc * a2;
    M[i * DG + j] = m;
    __syncthreads();

    float t = 0.f;
    #pragma unroll
    for (int k = 0; k < DG; k++) t += M[i * DG + k] * M[k * DG + j];
    T[i * DG + j] = t;
    __syncthreads();

    float p = 0.f;
    #pragma unroll
    for (int k = 0; k < DG; k++) p += T[i * DG + k] * T[k * DG + j];
    g_Pt[g * DG * DG + j * DG + i] = p;
}

// ---------------------------------------------------------------------------
// Fused: norm -> packed u-recursion Chebyshev -> K-packed P matvec.
// Template MASKED: boundary chunks (0, 4) mask; interior chunks (1-3) don't.
// CTA = (chunk, g, b). 256 threads = 8 warps.
// ---------------------------------------------------------------------------
template<bool MASKED>
__global__ void __launch_bounds__(256) fused5(
    const float* __restrict__ x, const float* __restrict__ cheb,
    float* __restrict__ out)
{
    const int chn = MASKED ? (int)blockIdx.x * 4 : (int)blockIdx.x + 1;
    const int g   = blockIdx.y;
    const int b   = blockIdx.z;
    const int w0  = chn * CUSE - HALO;

    __shared__ float2 xs2[16 * PR2];                   // pair-interleaved x-plane
    __shared__ __align__(16) float ys[SPAN * YROW];    // y-plane (token-major)
    __shared__ float Ps[DG * DG];
    __shared__ float cc[Kc];

    const int tid  = threadIdx.x;
    const int lane = tid & 31;
    const int wp   = tid >> 5;

    for (int e = tid; e < DG * DG; e += 256) Ps[e] = g_Pt[g * DG * DG + e];
    // sign-flipped coefs for u-recursion: u_k = (-1)^k t_k
    if (tid < Kc) cc[tid] = cheb[g * Kc + tid] * ((tid & 1) ? -1.f : 1.f);

    // ---- Phase A: float4 load + octet norm -> pair plane (2x STS.64) ----
    const int a8   = lane & 7;
    const int tsub = lane >> 3;
    const int cp0  = a8 * 2;
    const float* xg = x + ((size_t)b * Wn) * Dn + g * DG + a8 * 4;
    #pragma unroll
    for (int p = 0; p < 4; p++) {
        int t = wp * 16 + p * 4 + tsub;
        int w = w0 + t;
        float4 v;
        if (MASKED) {
            v = make_float4(0.f, 0.f, 0.f, 0.f);
            if (w >= 0 && w < Wn) v = *(const float4*)(xg + (size_t)w * Dn);
        } else {
            v = *(const float4*)(xg + (size_t)w * Dn);
        }
        float s1 = v.x + v.y + v.z + v.w;
        float s2 = v.x * v.x + v.y * v.y + v.z * v.z + v.w * v.w;
        #pragma unroll
        for (int o = 1; o < 8; o <<= 1) {
            s1 += __shfl_xor_sync(0xffffffffu, s1, o);
            s2 += __shfl_xor_sync(0xffffffffu, s2, o);
        }
        float mean = s1 * (1.f / DG);
        float var  = s2 * (1.f / DG) - mean * mean;
        float rstd = rsqrtf(var + 1e-6f);
        int T = t + (t >> 2);
        xs2[cp0 * PR2 + T]       = make_float2((v.x - mean) * rstd, (v.y - mean) * rstd);
        xs2[(cp0 + 1) * PR2 + T] = make_float2((v.z - mean) * rstd, (v.w - mean) * rstd);
    }
    __syncthreads();

    // ---- Phase B: channel-pair packed u-recursion ----
    u64x2 NEG2, H2;
    PK2(NEG2, -1.f, -1.f);
    PK2(H2, 0.5f, 0.5f);
    u64x2 cc2[Kc];
    #pragma unroll
    for (int k = 0; k < Kc; k++) PK2(cc2[k], cc[k], cc[k]);

    u64x2 mk2[MASKED ? TPL : 1];
    if (MASKED) {
        #pragma unroll
        for (int i = 0; i < TPL; i++) {
            int w = w0 + 4 * lane + i;
            float m = (w >= 0 && w < Wn) ? 1.f : 0.f;
            PK2(mk2[i], m, m);
        }
    }
    const int swb    = 4 * a8;
    const bool storeY = (lane >= 2 && lane < 30);   // only central tokens needed

    #pragma unroll
    for (int p2 = 0; p2 < 2; p2++) {
        const int cp = wp * 2 + p2;                 // channel-pair index
        const int cA = cp * 2;                      // even channel
        u64x2 X2[TPL], T2[TPL], y2[TPL];

        #pragma unroll
        for (int i = 0; i < TPL; i++)
            X2[i] = *(const u64x2*)&xs2[cp * PR2 + 5 * lane + i];

        // u1 = 0.5*(L+R) (masked); y = cc0*u0 + cc1*u1
        {
            u64x2 lh2 = __shfl_up_sync(0xffffffffu, X2[TPL - 1], 1);
            u64x2 rh2 = __shfl_down_sync(0xffffffffu, X2[0], 1);
            if (lane == 0)  lh2 = 0ull;
            if (lane == 31) rh2 = 0ull;
            #pragma unroll
            for (int i = 0; i < TPL; i++) {
                u64x2 L = (i > 0)       ? X2[i - 1] : lh2;
                u64x2 R = (i < TPL - 1) ? X2[i + 1] : rh2;
                u64x2 s; ADD2(s, L, R);
                MUL2(s, s, H2);
                if (MASKED) MUL2(s, s, mk2[i]);
                T2[i] = s;
                u64x2 tmp; MUL2(tmp, cc2[0], X2[i]);
                FMA2(y2[i], cc2[1], T2[i], tmp);
            }
        }

        // u_k = (L+R) - u_{k-2} (masked); y += cc_k * u_k
        #define STEPP(PV, CU, CK2)                                            \
        {                                                                     \
            u64x2 lh2 = __shfl_up_sync(0xffffffffu, CU[TPL - 1], 1);          \
            u64x2 rh2 = __shfl_down_sync(0xffffffffu, CU[0], 1);              \
            if (lane == 0)  lh2 = 0ull;                                       \
            if (lane == 31) rh2 = 0ull;                                       \
            _Pragma("unroll")                                                 \
            for (int i = 0; i < TPL; i++) {                                   \
                u64x2 L = (i > 0)       ? CU[i - 1] : lh2;                    \
                u64x2 R = (i < TPL - 1) ? CU[i + 1] : rh2;                    \
                u64x2 s; ADD2(s, L, R);                                       \
                u64x2 nt; FMA2(nt, PV[i], NEG2, s);                           \
                if (MASKED) MUL2(nt, nt, mk2[i]);                             \
                FMA2(y2[i], CK2, nt, y2[i]);                                  \
                PV[i] = nt;                                                   \
            }                                                                 \
        }
        STEPP(X2, T2, cc2[2])
        STEPP(T2, X2, cc2[3])
        STEPP(X2, T2, cc2[4])
        STEPP(T2, X2, cc2[5])
        STEPP(X2, T2, cc2[6])
        STEPP(T2, X2, cc2[7])
        STEPP(X2, T2, cc2[8])
        #undef STEPP

        // store y pair (STS.64), swizzled; halo lanes skip
        if (storeY) {
            #pragma unroll
            for (int i = 0; i < TPL; i++) {
                float lo, hi;
                UPK2(lo, hi, y2[i]);
                int fo = (4 * lane + i) * YROW + (cA ^ swb);
                *(float2*)&ys[fo] = make_float2(lo, hi);
            }
        }
    }
    __syncthreads();

    // ---- Phase C: z = P*y, K-packed f32x2. Warp per token, lane = channel ----
    u64x2 pa[8], pb[8];
    #pragma unroll
    for (int k = 0; k < 8; k++) {
        PK2(pa[k], Ps[(4 * k + 0) * DG + lane], Ps[(4 * k + 1) * DG + lane]);
        PK2(pb[k], Ps[(4 * k + 2) * DG + lane], Ps[(4 * k + 3) * DG + lane]);
    }
    const uint32_t ysb = (uint32_t)__cvta_generic_to_shared(ys);
    float* ob = out + ((size_t)b * Wn) * Dn + g * DG + lane;

    #pragma unroll
    for (int t = HALO + 0; t < HALO + CUSE; t += 8) {
        int tt = t + wp;
        int w  = w0 + tt;
        if (MASKED && w >= Wn) break;               // trims only the last chunk
        const int sw = (tt >> 2) & 7;
        const uint32_t ba = ysb + (uint32_t)tt * (YROW * 4);
        u64x2 a0 = 0ull, a1 = 0ull;
        #pragma unroll
        for (int k = 0; k < 8; k++) {
            uint32_t ad = ba + 16u * (uint32_t)(k ^ sw);
            u64x2 ya, yb;
            asm volatile("ld.shared.v2.u64 {%0,%1},[%2];"
                         : "=l"(ya), "=l"(yb) : "r"(ad));
            FMA2(a0, ya, pa[k], a0);
            FMA2(a1, yb, pb[k], a1);
        }
        float x0, x1, x2, x3;
        UPK2(x0, x1, a0);
        UPK2(x2, x3, a1);
        ob[(size_t)w * Dn] = (x0 + x1) + (x2 + x3);
    }
}

extern "C" void kernel_launch(void* const* d_in, const int* in_sizes, int n_in,
                              void* d_out, int out_size)
{
    const float* x    = (const float*)d_in[0];
    const float* cheb = (const float*)d_in[1];
    const float* U    = (const float*)d_in[2];
    const float* V    = (const float*)d_in[3];
    const float* S    = (const float*)d_in[4];
    float* out        = (float*)d_out;

    precompute_P<<<Gn, 1024>>>(U, V, S);
    dim3 gridU(3, Gn, Bn);      // interior chunks 1..3, no masking
    fused5<false><<<gridU, 256>>>(x, cheb, out);
    dim3 gridM(2, Gn, Bn);      // boundary chunks 0 and 4
    fused5<true><<<gridM, 256>>>(x, cheb, out);
}